// round 4
// baseline (speedup 1.0000x reference)
#include <cuda_runtime.h>
#include <cuda_bf16.h>
#include <cstdint>

// Problem dims
#define TT 2048
#define BB 16
#define II 512
#define HH 512
#define BH (BB*HH)   // 8192

#define GROUPS 4
#define GCTAS  32

// Per-CTA progress flags: flags[group][cta_in_group] = number of steps published.
// Reset by xproj_kernel (stream-ordered before the scan each launch/replay).
__device__ unsigned int g_flags[GROUPS][GCTAS];

static __device__ __forceinline__ unsigned int ld_acquire_gpu(const unsigned int* p) {
    unsigned int v;
    asm volatile("ld.acquire.gpu.u32 %0, [%1];" : "=r"(v) : "l"(p) : "memory");
    return v;
}
static __device__ __forceinline__ void st_release_gpu(unsigned int* p, unsigned int v) {
    asm volatile("st.release.gpu.u32 [%0], %1;" :: "l"(p), "r"(v) : "memory");
}

// ---------------------------------------------------------------------------
// Kernel 1: x_proj[t,b,h] = sum_i inputs[t,b,i] * w_xh[h][i] + bias[h]
// GEMM M=32768, N=512, K=512. 128x64 tile, 256 threads, 8x4 microtile.
// ---------------------------------------------------------------------------
__global__ __launch_bounds__(256)
void xproj_kernel(const float* __restrict__ A,      // inputs [M][512]
                  const float* __restrict__ W,      // weight [512][1024]
                  const float* __restrict__ bias,   // [512]
                  float* __restrict__ out)          // [M][512]
{
    // reset scan flags (stream-ordered before the scan kernel)
    if (blockIdx.x == 0 && blockIdx.y == 0 && threadIdx.x < GROUPS * GCTAS)
        (&g_flags[0][0])[threadIdx.x] = 0u;

    __shared__ float As[32][132];  // [k][m], padded
    __shared__ float Bs[32][68];   // [k][n], padded

    const int tid = threadIdx.x;
    const int bm = blockIdx.x * 128;
    const int bn = blockIdx.y * 64;

    const int tx = tid & 15;   // n group
    const int ty = tid >> 4;   // m group

    float acc[8][4];
#pragma unroll
    for (int r = 0; r < 8; r++)
#pragma unroll
        for (int c = 0; c < 4; c++) acc[r][c] = 0.f;

#pragma unroll 1
    for (int kt = 0; kt < 16; kt++) {
        const int k0 = kt * 32;
#pragma unroll
        for (int j = 0; j < 4; j++) {
            int idx = tid + j * 256;
            int row = idx >> 3;
            int q   = idx & 7;
            float4 v = *reinterpret_cast<const float4*>(&A[(size_t)(bm + row) * 512 + k0 + q * 4]);
            As[q * 4 + 0][row] = v.x;
            As[q * 4 + 1][row] = v.y;
            As[q * 4 + 2][row] = v.z;
            As[q * 4 + 3][row] = v.w;
        }
#pragma unroll
        for (int j = 0; j < 2; j++) {
            int idx = tid + j * 256;
            int row = idx >> 3;
            int q   = idx & 7;
            float4 v = *reinterpret_cast<const float4*>(&W[(size_t)(bn + row) * 1024 + 512 + k0 + q * 4]);
            Bs[q * 4 + 0][row] = v.x;
            Bs[q * 4 + 1][row] = v.y;
            Bs[q * 4 + 2][row] = v.z;
            Bs[q * 4 + 3][row] = v.w;
        }
        __syncthreads();

#pragma unroll
        for (int k = 0; k < 32; k++) {
            float4 a0 = *reinterpret_cast<const float4*>(&As[k][ty * 8]);
            float4 a1 = *reinterpret_cast<const float4*>(&As[k][ty * 8 + 4]);
            float4 b  = *reinterpret_cast<const float4*>(&Bs[k][tx * 4]);
            float av[8] = {a0.x, a0.y, a0.z, a0.w, a1.x, a1.y, a1.z, a1.w};
            float bv[4] = {b.x, b.y, b.z, b.w};
#pragma unroll
            for (int r = 0; r < 8; r++)
#pragma unroll
                for (int c = 0; c < 4; c++)
                    acc[r][c] = fmaf(av[r], bv[c], acc[r][c]);
        }
        __syncthreads();
    }

#pragma unroll
    for (int r = 0; r < 8; r++) {
        size_t row = (size_t)(bm + ty * 8 + r) * 512 + bn + tx * 4;
#pragma unroll
        for (int c = 0; c < 4; c++)
            out[row + c] = acc[r][c] + bias[bn + tx * 4 + c];
    }
}

// ---------------------------------------------------------------------------
// Kernel 2: persistent scan, latency-optimized protocol.
// 128 CTAs = 4 batch-groups x 32 col-groups. W_hh slice in SMEM.
// Per step:
//   - all warps poll the 32 per-CTA flags (one coalesced 128B acquire load)
//   - stage h_{t-1} (ldcg -> double-buffered SMEM)
//   - syncthreads (A); FMA; shfl.bfly(16) pair-combine; STS partials
//   - syncthreads (B); warps 0-1 reduce 8-deep, add prefetched xp,
//     stg.cg h_t, bar.sync(1,64), tid0 st.release flag = t+1.
//   Warps 2-7 overlap step t's publish with step t+1's poll + h staging.
// ---------------------------------------------------------------------------
__global__ __launch_bounds__(256)
void scan_kernel(const float* __restrict__ weight,  // [512][1024], w_hh = cols [0,512)
                 const float* __restrict__ state,   // [16][512]
                 float* __restrict__ out)           // [T][16][512] + last [16][512]
{
    __shared__ float Wsh[512][16];     // [k][col]  32 KB
    __shared__ float hsh[2][4][512];   // double-buffered h  16 KB
    __shared__ float red[2][8][64];    // double-buffered partials  4 KB

    const int tid  = threadIdx.x;
    const int lane = tid & 31;
    const int warp = tid >> 5;
    const int cg   = blockIdx.x & 31;   // cols [cg*16, cg*16+16)
    const int bg   = blockIdx.x >> 5;   // batches [bg*4, bg*4+4)
    const int b0   = bg * 4;

    const int col   = tid & 15;
    const int ks    = tid >> 4;         // 16 k-splits of 32
    const int kbase = ks * 32;

    // Load W_hh slice once: Wsh[k][c] = weight[(cg*16+c)][k]
    {
        const int c  = tid & 15;
        const int kk = tid >> 4;
#pragma unroll
        for (int j = 0; j < 8; j++) {
            int k = kk * 32 + j * 4;
            float4 w = *reinterpret_cast<const float4*>(&weight[(size_t)(cg * 16 + c) * 1024 + k]);
            Wsh[k + 0][c] = w.x;
            Wsh[k + 1][c] = w.y;
            Wsh[k + 2][c] = w.z;
            Wsh[k + 3][c] = w.w;
        }
    }
    __syncthreads();

    unsigned int* flags = g_flags[bg];

    // Reducer threads (tid<64) own one output element (rc, rb) each.
    const int rc = tid & 15;
    const int rb = (tid >> 4) & 3;
    const size_t rbase = (size_t)(b0 + rb) * HH + (size_t)cg * 16 + rc;

    // Prefetch x_proj for t=0 (written by xproj_kernel, stream-ordered).
    float xp = (tid < 64) ? __ldcg(out + rbase) : 0.f;

#pragma unroll 1
    for (int t = 0; t < TT; t++) {
        const int buf = t & 1;

        // ---- 1. wait for h_{t-1} from all 32 CTAs in this group ----
        if (t > 0) {
            const unsigned int tgt = (unsigned int)t;
            for (;;) {
                unsigned int v = ld_acquire_gpu(&flags[lane]);
                if (__all_sync(0xffffffffu, v >= tgt)) break;
            }
        }

        // ---- 2. stage h_{t-1} into SMEM (L2-only) ----
        const float* hsrc = (t == 0) ? (state + (size_t)b0 * HH)
                                     : (out + (size_t)(t - 1) * BH + (size_t)b0 * HH);
        {
            float4 v0 = __ldcg(reinterpret_cast<const float4*>(hsrc) + tid);
            float4 v1 = __ldcg(reinterpret_cast<const float4*>(hsrc) + tid + 256);
            reinterpret_cast<float4*>(&hsh[buf][0][0])[tid]       = v0;
            reinterpret_cast<float4*>(&hsh[buf][0][0])[tid + 256] = v1;
        }
        __syncthreads();   // (A)

        // ---- 3. partial dot products over k in [kbase, kbase+32) ----
        float acc0 = 0.f, acc1 = 0.f, acc2 = 0.f, acc3 = 0.f;
#pragma unroll
        for (int kc = 0; kc < 8; kc++) {
            const int k = kbase + kc * 4;
            float4 h0 = *reinterpret_cast<const float4*>(&hsh[buf][0][k]);
            float4 h1 = *reinterpret_cast<const float4*>(&hsh[buf][1][k]);
            float4 h2 = *reinterpret_cast<const float4*>(&hsh[buf][2][k]);
            float4 h3 = *reinterpret_cast<const float4*>(&hsh[buf][3][k]);
            float w0 = Wsh[k + 0][col];
            float w1 = Wsh[k + 1][col];
            float w2 = Wsh[k + 2][col];
            float w3 = Wsh[k + 3][col];
            acc0 = fmaf(w0, h0.x, acc0); acc0 = fmaf(w1, h0.y, acc0);
            acc0 = fmaf(w2, h0.z, acc0); acc0 = fmaf(w3, h0.w, acc0);
            acc1 = fmaf(w0, h1.x, acc1); acc1 = fmaf(w1, h1.y, acc1);
            acc1 = fmaf(w2, h1.z, acc1); acc1 = fmaf(w3, h1.w, acc1);
            acc2 = fmaf(w0, h2.x, acc2); acc2 = fmaf(w1, h2.y, acc2);
            acc2 = fmaf(w2, h2.z, acc2); acc2 = fmaf(w3, h2.w, acc2);
            acc3 = fmaf(w0, h3.x, acc3); acc3 = fmaf(w1, h3.y, acc3);
            acc3 = fmaf(w2, h3.z, acc3); acc3 = fmaf(w3, h3.w, acc3);
        }

        // ---- 4. combine the two k-splits of this warp via shuffle ----
        acc0 += __shfl_xor_sync(0xffffffffu, acc0, 16);
        acc1 += __shfl_xor_sync(0xffffffffu, acc1, 16);
        acc2 += __shfl_xor_sync(0xffffffffu, acc2, 16);
        acc3 += __shfl_xor_sync(0xffffffffu, acc3, 16);
        if (lane < 16)
            *reinterpret_cast<float4*>(&red[buf][warp][lane * 4]) =
                make_float4(acc0, acc1, acc2, acc3);
        __syncthreads();   // (B)

        // ---- 5. final reduce + publish (warps 0-1 only; others race ahead) ----
        if (tid < 64) {
            float s = 0.f;
#pragma unroll
            for (int w = 0; w < 8; w++) s += red[buf][w][rc * 4 + rb];
            const float hn = s + xp;
            const size_t off = (size_t)t * BH + rbase;
            __stcg(out + off, hn);
            if (t == TT - 1)
                __stcg(out + (size_t)TT * BH + rbase, hn);
            // prefetch x_proj for t+1 (still untouched in out[])
            if (t + 1 < TT)
                xp = __ldcg(out + (size_t)(t + 1) * BH + rbase);
            // order the 64 h-stores before the flag publish
            asm volatile("bar.sync 1, 64;" ::: "memory");
            if (tid == 0)
                st_release_gpu(&flags[cg], (unsigned int)(t + 1));
        }
    }
}

// ---------------------------------------------------------------------------
// Launch
// ---------------------------------------------------------------------------
extern "C" void kernel_launch(void* const* d_in, const int* in_sizes, int n_in,
                              void* d_out, int out_size) {
    const float* inputs = (const float*)d_in[0];  // [T][B][I]
    const float* state  = (const float*)d_in[1];  // [B][H]
    const float* weight = (const float*)d_in[2];  // [H][I+H]
    const float* bias   = (const float*)d_in[3];  // [H]
    float* out = (float*)d_out;                   // [T][B][H] outputs, then [B][H] last

    dim3 g1(256, 8);  // M/128 x N/64
    xproj_kernel<<<g1, 256>>>(inputs, weight, bias, out);

    scan_kernel<<<GROUPS * GCTAS, 256>>>(weight, state, out);

    (void)in_sizes; (void)n_in; (void)out_size;
}

// round 5
// speedup vs baseline: 4.5971x; 4.5971x over previous
#include <cuda_runtime.h>
#include <cuda_bf16.h>
#include <cstdint>

typedef unsigned long long u64;

// Problem dims
#define TT 2048
#define BB 16
#define II 512
#define HH 512
#define BH (BB*HH)   // 8192

#define CLUSTER 8    // CTAs per cluster = 1 batch per cluster, 64 cols per CTA

static __device__ __forceinline__ uint32_t smem_u32(const void* p) {
    uint32_t a;
    asm("{ .reg .u64 t; cvta.to.shared.u64 t, %1; cvt.u32.u64 %0, t; }"
        : "=r"(a) : "l"(p));
    return a;
}

// ---------------------------------------------------------------------------
// Kernel 1: x_proj[t,b,h] = sum_i inputs[t,b,i] * w_xh[h][i] + bias[h]
// GEMM M=32768, N=512, K=512. 128x64 tile, 256 threads, 8x4 microtile.
// (unchanged from the 5735us round — proven, ~85% fma-bound)
// ---------------------------------------------------------------------------
__global__ __launch_bounds__(256)
void xproj_kernel(const float* __restrict__ A,      // inputs [M][512]
                  const float* __restrict__ W,      // weight [512][1024]
                  const float* __restrict__ bias,   // [512]
                  float* __restrict__ out)          // [M][512]
{
    __shared__ float As[32][132];  // [k][m], padded
    __shared__ float Bs[32][68];   // [k][n], padded

    const int tid = threadIdx.x;
    const int bm = blockIdx.x * 128;
    const int bn = blockIdx.y * 64;

    const int tx = tid & 15;   // n group
    const int ty = tid >> 4;   // m group

    float acc[8][4];
#pragma unroll
    for (int r = 0; r < 8; r++)
#pragma unroll
        for (int c = 0; c < 4; c++) acc[r][c] = 0.f;

#pragma unroll 1
    for (int kt = 0; kt < 16; kt++) {
        const int k0 = kt * 32;
#pragma unroll
        for (int j = 0; j < 4; j++) {
            int idx = tid + j * 256;
            int row = idx >> 3;
            int q   = idx & 7;
            float4 v = *reinterpret_cast<const float4*>(&A[(size_t)(bm + row) * 512 + k0 + q * 4]);
            As[q * 4 + 0][row] = v.x;
            As[q * 4 + 1][row] = v.y;
            As[q * 4 + 2][row] = v.z;
            As[q * 4 + 3][row] = v.w;
        }
#pragma unroll
        for (int j = 0; j < 2; j++) {
            int idx = tid + j * 256;
            int row = idx >> 3;
            int q   = idx & 7;
            float4 v = *reinterpret_cast<const float4*>(&W[(size_t)(bn + row) * 1024 + 512 + k0 + q * 4]);
            Bs[q * 4 + 0][row] = v.x;
            Bs[q * 4 + 1][row] = v.y;
            Bs[q * 4 + 2][row] = v.z;
            Bs[q * 4 + 3][row] = v.w;
        }
        __syncthreads();

#pragma unroll
        for (int k = 0; k < 32; k++) {
            float4 a0 = *reinterpret_cast<const float4*>(&As[k][ty * 8]);
            float4 a1 = *reinterpret_cast<const float4*>(&As[k][ty * 8 + 4]);
            float4 b  = *reinterpret_cast<const float4*>(&Bs[k][tx * 4]);
            float av[8] = {a0.x, a0.y, a0.z, a0.w, a1.x, a1.y, a1.z, a1.w};
            float bv[4] = {b.x, b.y, b.z, b.w};
#pragma unroll
            for (int r = 0; r < 8; r++)
#pragma unroll
                for (int c = 0; c < 4; c++)
                    acc[r][c] = fmaf(av[r], bv[c], acc[r][c]);
        }
        __syncthreads();
    }

#pragma unroll
    for (int r = 0; r < 8; r++) {
        size_t row = (size_t)(bm + ty * 8 + r) * 512 + bn + tx * 4;
#pragma unroll
        for (int c = 0; c < 4; c++)
            out[row + c] = acc[r][c] + bias[bn + tx * 4 + c];
    }
}

// ---------------------------------------------------------------------------
// Kernel 2: cluster-based persistent scan.
// Grid = 128 CTAs = 16 clusters of 8. Cluster c owns batch b=c; CTA rank r
// owns output columns [r*64, r*64+64).
//
// Per CTA: 512 threads, thread (col = tid&63, ks = tid>>6).
// W_hh[gcol][ks*64 .. +64) lives in 32 packed f32x2 REGISTERS (loaded once).
// h_{t-1} lives in double-buffered SMEM hsh[2][512], filled by DSMEM pushes
// from the producing CTAs of the cluster.
//
// Step t:
//   compute: acc += w (f32x2) * h (ulonglong2 from smem broadcast)   ~384 cyc
//   __syncthreads; 64 threads reduce 8 k-splits from smem
//   fan out h_t col to all 8 CTAs' hsh[next] via st.shared::cluster
//   barrier.cluster.arrive (release covers DSMEM stores)
//   store out[t], prefetch x_proj[t+1]  (overlapped with barrier)
//   barrier.cluster.wait
// ---------------------------------------------------------------------------
__global__ void __cluster_dims__(CLUSTER, 1, 1) __launch_bounds__(512, 1)
scan_kernel(const float* __restrict__ weight,  // [512][1024], w_hh = cols [0,512)
            const float* __restrict__ state,   // [16][512]
            float* __restrict__ out)           // [T][16][512] + last [16][512]
{
    __shared__ float hsh[2][512];   // double-buffered h (4 KB)
    __shared__ float red[8][65];    // k-split partials, padded (2.1 KB)

    const int tid  = threadIdx.x;
    const int col  = tid & 63;          // local column
    const int ks   = tid >> 6;          // k-split 0..7, k in [ks*64, ks*64+64)
    const int rank = blockIdx.x & (CLUSTER - 1);
    const int b    = blockIdx.x / CLUSTER;    // batch
    const int c0   = rank * 64;
    const int gcol = c0 + col;

    // ---- load W_hh slice into registers, packed as f32x2 pairs over k ----
    u64 wreg[32];
    {
        const u64* wp = reinterpret_cast<const u64*>(
            weight + (size_t)gcol * 1024 + ks * 64);
#pragma unroll
        for (int j = 0; j < 32; j += 2) {
            ulonglong2 v = *reinterpret_cast<const ulonglong2*>(wp + j);
            wreg[j]     = v.x;
            wreg[j + 1] = v.y;
        }
    }

    // ---- h_0 = state[b] ----
    hsh[0][tid] = state[(size_t)b * 512 + tid];
    __syncthreads();

    // ---- prefetch x_proj for t=0 (finalize threads tid<64 own col=tid) ----
    float xp = 0.f;
    if (tid < 64)
        xp = __ldcg(out + (size_t)b * 512 + c0 + tid);

    const uint32_t laddr_h1 = smem_u32(&hsh[1][gcol]);
    const uint32_t laddr_h0 = smem_u32(&hsh[0][gcol]);

#pragma unroll 1
    for (int t = 0; t < TT; t++) {
        const int rb = t & 1;

        // ---- compute: packed f32x2 dot over 64 k's ----
        u64 accp = 0ull;   // (0.f, 0.f)
        const u64* hp = reinterpret_cast<const u64*>(&hsh[rb][ks * 64]);
#pragma unroll
        for (int j = 0; j < 32; j += 2) {
            ulonglong2 h2 = *reinterpret_cast<const ulonglong2*>(hp + j);
            asm("fma.rn.f32x2 %0, %1, %2, %0;"
                : "+l"(accp) : "l"(wreg[j]),     "l"(h2.x));
            asm("fma.rn.f32x2 %0, %1, %2, %0;"
                : "+l"(accp) : "l"(wreg[j + 1]), "l"(h2.y));
        }
        {
            uint32_t lo, hi;
            asm("mov.b64 {%0, %1}, %2;" : "=r"(lo), "=r"(hi) : "l"(accp));
            red[ks][col] = __uint_as_float(lo) + __uint_as_float(hi);
        }
        __syncthreads();

        // ---- finalize: reduce 8 k-splits, fan out h_t via DSMEM ----
        float hn = 0.f;
        if (tid < 64) {
            float s = 0.f;
#pragma unroll
            for (int r = 0; r < 8; r++) s += red[r][tid];
            hn = s + xp;

            // push h_t[gcol] into every cluster CTA's hsh[rb^1]
            const uint32_t laddr = (rb ? laddr_h0 : laddr_h1);
#pragma unroll
            for (int r = 0; r < CLUSTER; r++) {
                uint32_t raddr;
                asm volatile("mapa.shared::cluster.u32 %0, %1, %2;"
                             : "=r"(raddr) : "r"(laddr), "r"(r));
                asm volatile("st.shared::cluster.f32 [%0], %1;"
                             :: "r"(raddr), "f"(hn) : "memory");
            }
        }

        // release-arrive: orders the DSMEM stores before peers' wait-acquire
        asm volatile("barrier.cluster.arrive.aligned;" ::: "memory");

        // overlapped with barrier: global out-store + next xp prefetch
        if (tid < 64) {
            const size_t off = (size_t)t * BH + (size_t)b * HH + c0 + tid;
            __stcg(out + off, hn);
            if (t == TT - 1)
                __stcg(out + (size_t)TT * BH + (size_t)b * HH + c0 + tid, hn);
            if (t + 1 < TT)
                xp = __ldcg(out + (size_t)(t + 1) * BH + (size_t)b * HH + c0 + tid);
        }

        asm volatile("barrier.cluster.wait.aligned;" ::: "memory");
    }
}

// ---------------------------------------------------------------------------
// Launch
// ---------------------------------------------------------------------------
extern "C" void kernel_launch(void* const* d_in, const int* in_sizes, int n_in,
                              void* d_out, int out_size) {
    const float* inputs = (const float*)d_in[0];  // [T][B][I]
    const float* state  = (const float*)d_in[1];  // [B][H]
    const float* weight = (const float*)d_in[2];  // [H][I+H]
    const float* bias   = (const float*)d_in[3];  // [H]
    float* out = (float*)d_out;                   // [T][B][H] outputs, then [B][H] last

    dim3 g1(256, 8);  // M/128 x N/64
    xproj_kernel<<<g1, 256>>>(inputs, weight, bias, out);

    // 16 clusters x 8 CTAs (cluster dims are compile-time via __cluster_dims__)
    scan_kernel<<<BB * CLUSTER, 512>>>(weight, state, out);

    (void)in_sizes; (void)n_in; (void)out_size;
}

// round 7
// speedup vs baseline: 6.6998x; 1.4574x over previous
#include <cuda_runtime.h>
#include <cuda_bf16.h>
#include <cstdint>

typedef unsigned long long u64;

// Problem dims
#define TT 2048
#define BB 16
#define II 512
#define HH 512
#define BH (BB*HH)   // 8192

#define CLUSTER 8    // CTAs per cluster = 1 batch per cluster, 64 cols per CTA

static __device__ __forceinline__ uint32_t smem_u32(const void* p) {
    uint32_t a;
    asm("{ .reg .u64 t; cvta.to.shared.u64 t, %1; cvt.u32.u64 %0, t; }"
        : "=r"(a) : "l"(p));
    return a;
}

// ---------------------------------------------------------------------------
// Kernel 1: x_proj GEMM (unchanged; ~0.4ms, fma-bound)
// ---------------------------------------------------------------------------
__global__ __launch_bounds__(256)
void xproj_kernel(const float* __restrict__ A,      // inputs [M][512]
                  const float* __restrict__ W,      // weight [512][1024]
                  const float* __restrict__ bias,   // [512]
                  float* __restrict__ out)          // [M][512]
{
    __shared__ float As[32][132];
    __shared__ float Bs[32][68];

    const int tid = threadIdx.x;
    const int bm = blockIdx.x * 128;
    const int bn = blockIdx.y * 64;

    const int tx = tid & 15;
    const int ty = tid >> 4;

    float acc[8][4];
#pragma unroll
    for (int r = 0; r < 8; r++)
#pragma unroll
        for (int c = 0; c < 4; c++) acc[r][c] = 0.f;

#pragma unroll 1
    for (int kt = 0; kt < 16; kt++) {
        const int k0 = kt * 32;
#pragma unroll
        for (int j = 0; j < 4; j++) {
            int idx = tid + j * 256;
            int row = idx >> 3;
            int q   = idx & 7;
            float4 v = *reinterpret_cast<const float4*>(&A[(size_t)(bm + row) * 512 + k0 + q * 4]);
            As[q * 4 + 0][row] = v.x;
            As[q * 4 + 1][row] = v.y;
            As[q * 4 + 2][row] = v.z;
            As[q * 4 + 3][row] = v.w;
        }
#pragma unroll
        for (int j = 0; j < 2; j++) {
            int idx = tid + j * 256;
            int row = idx >> 3;
            int q   = idx & 7;
            float4 v = *reinterpret_cast<const float4*>(&W[(size_t)(bn + row) * 1024 + 512 + k0 + q * 4]);
            Bs[q * 4 + 0][row] = v.x;
            Bs[q * 4 + 1][row] = v.y;
            Bs[q * 4 + 2][row] = v.z;
            Bs[q * 4 + 3][row] = v.w;
        }
        __syncthreads();

#pragma unroll
        for (int k = 0; k < 32; k++) {
            float4 a0 = *reinterpret_cast<const float4*>(&As[k][ty * 8]);
            float4 a1 = *reinterpret_cast<const float4*>(&As[k][ty * 8 + 4]);
            float4 b  = *reinterpret_cast<const float4*>(&Bs[k][tx * 4]);
            float av[8] = {a0.x, a0.y, a0.z, a0.w, a1.x, a1.y, a1.z, a1.w};
            float bv[4] = {b.x, b.y, b.z, b.w};
#pragma unroll
            for (int r = 0; r < 8; r++)
#pragma unroll
                for (int c = 0; c < 4; c++)
                    acc[r][c] = fmaf(av[r], bv[c], acc[r][c]);
        }
        __syncthreads();
    }

#pragma unroll
    for (int r = 0; r < 8; r++) {
        size_t row = (size_t)(bm + ty * 8 + r) * 512 + bn + tx * 4;
#pragma unroll
        for (int c = 0; c < 4; c++)
            out[row + c] = acc[r][c] + bias[bn + tx * 4 + c];
    }
}

// ---------------------------------------------------------------------------
// Kernel 2: cluster scan with st.async + mbarrier sync (no cluster barrier
// in the loop). 16 clusters x 8 CTAs; cluster = 1 batch; CTA rank owns 64
// output columns; thread (col=tid&63, ks=tid>>6); W_hh slice in registers.
//
// Step t:
//   [t>0] tid0: mbarrier.arrive.expect_tx(full[t&1], 2048); all: try_wait
//   compute partial dots from hsh[t&1] (f32x2), write red[ks][col]
//   __syncthreads (only one per step)
//   tid<64: reduce 8 partials, hn = s + xp,
//           st.async hn -> all 8 CTAs' hsh[(t+1)&1][gcol] signaling full[(t+1)&1]
//           (skipped at t=TT-1), stg.cg out[t], prefetch xp[t+1]
// Back-pressure is implicit: a producer reaches step t+1's writes only after
// receiving ALL of h_t, which requires this CTA's publish, which follows all
// local reads of hsh/red for step t.
// ---------------------------------------------------------------------------
__global__ void __cluster_dims__(CLUSTER, 1, 1) __launch_bounds__(512, 1)
scan_kernel(const float* __restrict__ weight,  // [512][1024], w_hh = cols [0,512)
            const float* __restrict__ state,   // [16][512]
            float* __restrict__ out)           // [T][16][512] + last [16][512]
{
    __shared__ float hsh[2][512];              // double-buffered h (4 KB)
    __shared__ float red[8][65];               // k-split partials, padded
    __shared__ __align__(8) u64 mbar[2];       // full[buf] barriers

    const int tid  = threadIdx.x;
    const int col  = tid & 63;
    const int ks   = tid >> 6;                 // k in [ks*64, ks*64+64)
    const int rank = blockIdx.x & (CLUSTER - 1);
    const int b    = blockIdx.x / CLUSTER;     // batch
    const int c0   = rank * 64;
    const int gcol = c0 + col;

    // ---- W_hh slice into registers (f32x2-packed over k) ----
    u64 wreg[32];
    {
        const u64* wp = reinterpret_cast<const u64*>(
            weight + (size_t)gcol * 1024 + ks * 64);
#pragma unroll
        for (int j = 0; j < 32; j += 2) {
            ulonglong2 v = *reinterpret_cast<const ulonglong2*>(wp + j);
            wreg[j]     = v.x;
            wreg[j + 1] = v.y;
        }
    }

    // ---- init: h_0 local fill, barriers, cluster-wide visibility ----
    hsh[0][tid] = state[(size_t)b * 512 + tid];
    const uint32_t bar0 = smem_u32(&mbar[0]);
    const uint32_t bar1 = smem_u32(&mbar[1]);
    if (tid == 0) {
        asm volatile("mbarrier.init.shared.b64 [%0], 1;" :: "r"(bar0) : "memory");
        asm volatile("mbarrier.init.shared.b64 [%0], 1;" :: "r"(bar1) : "memory");
    }
    __syncthreads();
    asm volatile("barrier.cluster.arrive.aligned;" ::: "memory");
    asm volatile("barrier.cluster.wait.aligned;" ::: "memory");

    // ---- prefetch x_proj for t=0 ----
    float xp = 0.f;
    if (tid < 64)
        xp = __ldcg(out + (size_t)b * 512 + c0 + tid);

    const uint32_t laddr_h0  = smem_u32(&hsh[0][gcol]);
    const uint32_t laddr_h1  = smem_u32(&hsh[1][gcol]);

#pragma unroll 1
    for (int t = 0; t < TT; t++) {
        const int rb = t & 1;
        const uint32_t barw = rb ? bar1 : bar0;

        // ---- 1. wait for h_{t-1} (2048 tx bytes) ----
        if (t > 0) {
            if (tid == 0)
                asm volatile("mbarrier.arrive.expect_tx.shared.b64 _, [%0], 2048;"
                             :: "r"(barw) : "memory");
            const uint32_t parity = ((unsigned)(t - 1) >> 1) & 1u;
            uint32_t done;
            asm volatile(
                "{\n\t.reg .pred p;\n\t"
                "mbarrier.try_wait.parity.acquire.cta.shared::cta.b64 p, [%1], %2;\n\t"
                "selp.b32 %0, 1, 0, p;\n\t}"
                : "=r"(done) : "r"(barw), "r"(parity) : "memory");
            while (!done) {
                asm volatile(
                    "{\n\t.reg .pred p;\n\t"
                    "mbarrier.try_wait.parity.acquire.cta.shared::cta.b64 p, [%1], %2, 0x989680;\n\t"
                    "selp.b32 %0, 1, 0, p;\n\t}"
                    : "=r"(done) : "r"(barw), "r"(parity) : "memory");
            }
        }

        // ---- 2. compute: packed f32x2 dot over this thread's 64 k's ----
        u64 accp = 0ull;
        const u64* hp = reinterpret_cast<const u64*>(&hsh[rb][ks * 64]);
#pragma unroll
        for (int j = 0; j < 32; j += 2) {
            ulonglong2 h2 = *reinterpret_cast<const ulonglong2*>(hp + j);
            asm("fma.rn.f32x2 %0, %1, %2, %0;"
                : "+l"(accp) : "l"(wreg[j]),     "l"(h2.x));
            asm("fma.rn.f32x2 %0, %1, %2, %0;"
                : "+l"(accp) : "l"(wreg[j + 1]), "l"(h2.y));
        }
        {
            uint32_t lo, hi;
            asm("mov.b64 {%0, %1}, %2;" : "=r"(lo), "=r"(hi) : "l"(accp));
            red[ks][col] = __uint_as_float(lo) + __uint_as_float(hi);
        }
        __syncthreads();

        // ---- 3. finalize: reduce, publish via st.async, store out ----
        if (tid < 64) {
            float s = 0.f;
#pragma unroll
            for (int r = 0; r < 8; r++) s += red[r][tid];
            const float hn = s + xp;

            if (t + 1 < TT) {
                // push h_t[gcol] (gcol = c0 + tid here since col==tid) to all
                // 8 CTAs' hsh[rb^1], each store signaling that CTA's full bar.
                const uint32_t ldst = rb ? laddr_h0 : laddr_h1;   // buffer rb^1
                const uint32_t lbar = rb ? bar0 : bar1;
                // NOTE: for tid<64, gcol = c0 + tid; laddr_* were computed with
                // this thread's own gcol, correct.
#pragma unroll
                for (int r = 0; r < CLUSTER; r++) {
                    uint32_t raddr, rbar;
                    asm volatile("mapa.shared::cluster.u32 %0, %1, %2;"
                                 : "=r"(raddr) : "r"(ldst), "r"(r));
                    asm volatile("mapa.shared::cluster.u32 %0, %1, %2;"
                                 : "=r"(rbar) : "r"(lbar), "r"(r));
                    asm volatile(
                        "st.async.weak.shared::cluster.mbarrier::complete_tx::bytes.f32 [%0], %1, [%2];"
                        :: "r"(raddr), "f"(hn), "r"(rbar) : "memory");
                }
            }

            const size_t off = (size_t)t * BH + (size_t)b * HH + c0 + tid;
            __stcg(out + off, hn);
            if (t == TT - 1)
                __stcg(out + (size_t)TT * BH + (size_t)b * HH + c0 + tid, hn);
            if (t + 1 < TT)
                xp = __ldcg(out + (size_t)(t + 1) * BH + (size_t)b * HH + c0 + tid);
        }
    }

    // ---- drain: no CTA exits while peers might still target its SMEM ----
    asm volatile("barrier.cluster.arrive.aligned;" ::: "memory");
    asm volatile("barrier.cluster.wait.aligned;" ::: "memory");
}

// ---------------------------------------------------------------------------
// Launch
// ---------------------------------------------------------------------------
extern "C" void kernel_launch(void* const* d_in, const int* in_sizes, int n_in,
                              void* d_out, int out_size) {
    const float* inputs = (const float*)d_in[0];  // [T][B][I]
    const float* state  = (const float*)d_in[1];  // [B][H]
    const float* weight = (const float*)d_in[2];  // [H][I+H]
    const float* bias   = (const float*)d_in[3];  // [H]
    float* out = (float*)d_out;                   // [T][B][H] outputs, then [B][H] last

    dim3 g1(256, 8);
    xproj_kernel<<<g1, 256>>>(inputs, weight, bias, out);

    scan_kernel<<<BB * CLUSTER, 512>>>(weight, state, out);

    (void)in_sizes; (void)n_in; (void)out_size;
}